// round 2
// baseline (speedup 1.0000x reference)
#include <cuda_runtime.h>
#include <cuda_bf16.h>
#include <math.h>

// Problem dims (fixed by the dataset)
#define BATCH 256
#define TSTEPS 250
#define DIN 700
#define HID 1024
#define OUTD 20
#define MTOT (BATCH * TSTEPS)   // 64000

// ---------------------------------------------------------------------------
// Scratch: d1 = input @ W1^T + b1, layout [B*T, H] (row m = b*T + t)
// 64000 * 1024 floats = 262 MB static device allocation (no cudaMalloc allowed)
// ---------------------------------------------------------------------------
__device__ float g_d1[(size_t)MTOT * HID];

// ---------------------------------------------------------------------------
// SGEMM: C[m][n] = sum_k A[m][k] * W[n][k] + bias[n]
// A: [M, K] row-major (input flattened), W: [N, K] row-major (W1), C: [M, N]
// Tiles: BM=BN=128, BK=8, 256 threads, 8x8 per-thread microtile.
// M=64000 (%128==0), N=1024 (%128==0), K=700 (remainder guarded).
// ---------------------------------------------------------------------------
#define BM 128
#define BN 128
#define BKK 8

__global__ __launch_bounds__(256) void sgemm_bias_kernel(
    const float* __restrict__ A,
    const float* __restrict__ W,
    const float* __restrict__ bias,
    float* __restrict__ C,
    int M, int N, int K)
{
    __shared__ float As[BKK][BM];
    __shared__ float Bs[BKK][BN];

    const int tid = threadIdx.x;
    const int m0 = blockIdx.y * BM;
    const int n0 = blockIdx.x * BN;

    // microtile coords: 16x16 thread grid, each thread 8x8
    const int tx = tid & 15;   // N direction
    const int ty = tid >> 4;   // M direction

    // load coords: 256 threads load 128 rows x 8 cols (2 float4s per row)
    const int lrow  = tid >> 1;        // 0..127
    const int lcol4 = (tid & 1) * 4;   // 0 or 4

    float acc[8][8];
#pragma unroll
    for (int i = 0; i < 8; i++)
#pragma unroll
        for (int j = 0; j < 8; j++) acc[i][j] = 0.0f;

    for (int k0 = 0; k0 < K; k0 += BKK) {
        // ---- load A tile (transposed into As[k][m]) ----
        {
            const float* ap = A + (size_t)(m0 + lrow) * K + k0 + lcol4;
            float4 v;
            if (k0 + lcol4 + 3 < K) {
                v = *reinterpret_cast<const float4*>(ap);
            } else {
                v.x = (k0 + lcol4 + 0 < K) ? ap[0] : 0.0f;
                v.y = (k0 + lcol4 + 1 < K) ? ap[1] : 0.0f;
                v.z = (k0 + lcol4 + 2 < K) ? ap[2] : 0.0f;
                v.w = (k0 + lcol4 + 3 < K) ? ap[3] : 0.0f;
            }
            As[lcol4 + 0][lrow] = v.x;
            As[lcol4 + 1][lrow] = v.y;
            As[lcol4 + 2][lrow] = v.z;
            As[lcol4 + 3][lrow] = v.w;
        }
        // ---- load W tile (transposed into Bs[k][n]) ----
        {
            const float* bp = W + (size_t)(n0 + lrow) * K + k0 + lcol4;
            float4 v;
            if (k0 + lcol4 + 3 < K) {
                v = *reinterpret_cast<const float4*>(bp);
            } else {
                v.x = (k0 + lcol4 + 0 < K) ? bp[0] : 0.0f;
                v.y = (k0 + lcol4 + 1 < K) ? bp[1] : 0.0f;
                v.z = (k0 + lcol4 + 2 < K) ? bp[2] : 0.0f;
                v.w = (k0 + lcol4 + 3 < K) ? bp[3] : 0.0f;
            }
            Bs[lcol4 + 0][lrow] = v.x;
            Bs[lcol4 + 1][lrow] = v.y;
            Bs[lcol4 + 2][lrow] = v.z;
            Bs[lcol4 + 3][lrow] = v.w;
        }
        __syncthreads();

#pragma unroll
        for (int k = 0; k < BKK; k++) {
            float ar[8], br[8];
#pragma unroll
            for (int i = 0; i < 8; i++) ar[i] = As[k][ty * 8 + i];
#pragma unroll
            for (int j = 0; j < 8; j++) br[j] = Bs[k][tx * 8 + j];
#pragma unroll
            for (int i = 0; i < 8; i++)
#pragma unroll
                for (int j = 0; j < 8; j++)
                    acc[i][j] = fmaf(ar[i], br[j], acc[i][j]);
        }
        __syncthreads();
    }

    // ---- epilogue: add bias, store ----
    float bv[8];
#pragma unroll
    for (int j = 0; j < 8; j++) bv[j] = bias[n0 + tx * 8 + j];

#pragma unroll
    for (int i = 0; i < 8; i++) {
        float* cp = C + (size_t)(m0 + ty * 8 + i) * N + n0 + tx * 8;
        float4 o0, o1;
        o0.x = acc[i][0] + bv[0]; o0.y = acc[i][1] + bv[1];
        o0.z = acc[i][2] + bv[2]; o0.w = acc[i][3] + bv[3];
        o1.x = acc[i][4] + bv[4]; o1.y = acc[i][5] + bv[5];
        o1.z = acc[i][6] + bv[6]; o1.w = acc[i][7] + bv[7];
        *reinterpret_cast<float4*>(cp)     = o0;
        *reinterpret_cast<float4*>(cp + 4) = o1;
    }
}

// ---------------------------------------------------------------------------
// Scan kernel: one block per batch sample. 1024 threads = H.
//  - mem1[h] lives in a register (thread h)
//  - spikes go to shared each step
//  - warp o (o<20) owns W2 row o in 32 registers/thread, computes d2[o]
//  - warp 0 lanes 0..19 hold mem2/acc, do softmax via warp shuffles
// ---------------------------------------------------------------------------
__global__ __launch_bounds__(1024, 1) void scan_kernel(
    const float* __restrict__ d1,     // [B*T, H], bias already included
    const float* __restrict__ tau1,   // [H]
    const float* __restrict__ W2,     // [O, H]
    const float* __restrict__ b2,     // [O]
    const float* __restrict__ tau2,   // [O]
    float* __restrict__ out)          // [B, O]
{
    const int b    = blockIdx.x;
    const int h    = threadIdx.x;
    const int warp = h >> 5;
    const int lane = h & 31;

    __shared__ float spk_sh[HID];
    __shared__ float d2_sh[OUTD];

    // per-neuron layer-1 params
    const float a1  = 1.0f / (1.0f + expf(-tau1[h]));
    const float om1 = 1.0f - a1;

    // W2 row in registers for warps 0..19
    float w2r[32];
    if (warp < OUTD) {
#pragma unroll
        for (int i = 0; i < 32; i++)
            w2r[i] = W2[warp * HID + i * 32 + lane];
    }

    // layer-2 state on warp 0, lanes 0..19
    float mem2 = 0.0f, accum = 0.0f, a2 = 0.0f, om2 = 0.0f, bias2 = 0.0f;
    if (warp == 0 && lane < OUTD) {
        a2    = 1.0f / (1.0f + expf(-tau2[lane]));
        om2   = 1.0f - a2;
        bias2 = b2[lane];
    }

    float mem1 = 0.0f, spk = 0.0f;
    const float* d1b = d1 + (size_t)b * TSTEPS * HID + h;

    float dnext = d1b[0];   // prefetch t=0
    for (int t = 0; t < TSTEPS; t++) {
        const float d = dnext;
        if (t < TSTEPS - 1) dnext = d1b[(size_t)(t + 1) * HID];  // prefetch t+1

        // LIF layer 1 (soft reset), spike
        mem1 = mem1 * a1 + om1 * d - spk;
        spk  = (mem1 > 1.0f) ? 1.0f : 0.0f;
        spk_sh[h] = spk;
        __syncthreads();

        // d2[o] = sum_h spk[h] * W2[o][h]   (warp o)
        if (warp < OUTD) {
            float s = 0.0f;
#pragma unroll
            for (int i = 0; i < 32; i++)
                s = fmaf(spk_sh[i * 32 + lane], w2r[i], s);
#pragma unroll
            for (int o = 16; o > 0; o >>= 1)
                s += __shfl_xor_sync(0xffffffffu, s, o);
            if (lane == 0) d2_sh[warp] = s;
        }
        __syncthreads();

        // readout integrator + softmax accumulation (warp 0)
        if (warp == 0) {
            float val = -3.402823466e38f;
            if (lane < OUTD) {
                mem2 = mem2 * a2 + om2 * (d2_sh[lane] + bias2);
                val  = mem2;
            }
            float m = val;
#pragma unroll
            for (int o = 16; o > 0; o >>= 1)
                m = fmaxf(m, __shfl_xor_sync(0xffffffffu, m, o));
            float e = (lane < OUTD) ? expf(val - m) : 0.0f;
            float ssum = e;
#pragma unroll
            for (int o = 16; o > 0; o >>= 1)
                ssum += __shfl_xor_sync(0xffffffffu, ssum, o);
            if (t > 10 && lane < OUTD)
                accum += e / ssum;
        }
        __syncthreads();   // protect spk_sh / d2_sh for next step
    }

    if (warp == 0 && lane < OUTD)
        out[b * OUTD + lane] = accum;
}

// ---------------------------------------------------------------------------
// kernel_launch
// Inputs (metadata order): input_data[B,T,D], W1[H,D], b1[H], tau_m1[H],
//                          W2[O,H], b2[O], tau_m2[O].  Output: acc[B,O] fp32.
// ---------------------------------------------------------------------------
extern "C" void kernel_launch(void* const* d_in, const int* in_sizes, int n_in,
                              void* d_out, int out_size)
{
    const float* input = (const float*)d_in[0];
    const float* W1    = (const float*)d_in[1];
    const float* b1    = (const float*)d_in[2];
    const float* tau1  = (const float*)d_in[3];
    const float* W2    = (const float*)d_in[4];
    const float* b2    = (const float*)d_in[5];
    const float* tau2  = (const float*)d_in[6];
    float* out = (float*)d_out;

    float* d1;
    cudaGetSymbolAddress((void**)&d1, g_d1);

    // Phase 1: d1 = input @ W1^T + b1   (M=64000, N=1024, K=700)
    dim3 grid(HID / BN, MTOT / BM);   // (8, 500)
    sgemm_bias_kernel<<<grid, 256>>>(input, W1, b1, d1, MTOT, HID, DIN);

    // Phase 2: sequential scan, one block per batch sample
    scan_kernel<<<BATCH, HID>>>(d1, tau1, W2, b2, tau2, out);

    (void)in_sizes; (void)n_in; (void)out_size;
}

// round 6
// speedup vs baseline: 2.5672x; 2.5672x over previous
#include <cuda_runtime.h>
#include <cuda_bf16.h>
#include <math.h>
#include <stdint.h>

// Problem dims (fixed by the dataset)
#define BATCH 256
#define TSTEPS 250
#define DIN 700
#define KPAD 704            // DIN padded to multiple of 32
#define HID 1024
#define OUTD 20
#define MTOT (BATCH * TSTEPS)   // 64000
#define BKT 32                  // K per stage (bf16)
#define KT (KPAD / BKT)         // 22 k-tiles
#define STAGE_BYTES 32768       // 4 tiles x 128x32 bf16 (8 KB each)
#define NSTAGES 3

// ---------------------------------------------------------------------------
// Static scratch (no cudaMalloc allowed)
// ---------------------------------------------------------------------------
__device__ float         g_d1[(size_t)MTOT * KPAD ? (size_t)MTOT * HID : 0];
__device__ __nv_bfloat16 g_Ah[(size_t)MTOT * KPAD];
__device__ __nv_bfloat16 g_Al[(size_t)MTOT * KPAD];
__device__ __nv_bfloat16 g_Wh[(size_t)HID * KPAD];
__device__ __nv_bfloat16 g_Wl[(size_t)HID * KPAD];

// ---------------------------------------------------------------------------
// Portable PTX helpers (sm_80-era: cp.async, ldmatrix, mma.sync — all valid
// for base sm_103 target; NO tcgen05 anywhere)
// ---------------------------------------------------------------------------
__device__ __forceinline__ uint32_t smem_u32(const void* p) {
    uint32_t a;
    asm("{ .reg .u64 t; cvta.to.shared.u64 t, %1; cvt.u32.u64 %0, t; }" : "=r"(a) : "l"(p));
    return a;
}

#define CP16(dst, src) \
    asm volatile("cp.async.cg.shared.global [%0], [%1], 16;" \
                 :: "r"(dst), "l"(src) : "memory")

__device__ __forceinline__ void ldsm_x4(uint32_t addr, uint32_t& r0, uint32_t& r1,
                                        uint32_t& r2, uint32_t& r3) {
    asm volatile("ldmatrix.sync.aligned.m8n8.x4.shared.b16 {%0,%1,%2,%3}, [%4];"
                 : "=r"(r0), "=r"(r1), "=r"(r2), "=r"(r3) : "r"(addr));
}

__device__ __forceinline__ void mma_bf16(float* d, const uint32_t* a, const uint32_t* b) {
    asm volatile("mma.sync.aligned.m16n8k16.row.col.f32.bf16.bf16.f32 "
                 "{%0,%1,%2,%3}, {%4,%5,%6,%7}, {%8,%9}, {%0,%1,%2,%3};"
                 : "+f"(d[0]), "+f"(d[1]), "+f"(d[2]), "+f"(d[3])
                 : "r"(a[0]), "r"(a[1]), "r"(a[2]), "r"(a[3]), "r"(b[0]), "r"(b[1]));
}

// ---------------------------------------------------------------------------
// Prepass: fp32 [rows, DIN] -> bf16 hi/lo [rows, KPAD] (zero-padded cols)
// ---------------------------------------------------------------------------
__global__ void split_bf16_kernel(const float* __restrict__ src,
                                  __nv_bfloat16* __restrict__ hi,
                                  __nv_bfloat16* __restrict__ lo,
                                  int rows) {
    size_t total = (size_t)rows * KPAD;
    for (size_t i = (size_t)blockIdx.x * blockDim.x + threadIdx.x; i < total;
         i += (size_t)gridDim.x * blockDim.x) {
        size_t r = i / KPAD;
        int    k = (int)(i - r * KPAD);
        float  v = (k < DIN) ? src[r * DIN + k] : 0.0f;
        __nv_bfloat16 h = __float2bfloat16(v);
        __nv_bfloat16 l = __float2bfloat16(v - __bfloat162float(h));
        hi[i] = h;
        lo[i] = l;
    }
}

// ---------------------------------------------------------------------------
// HMMA GEMM: C[M=64000, N=1024] = A @ W^T + bias, 3-term split-bf16.
// CTA 128x128, BK=32, 3-stage cp.async pipeline, 8 warps (2m x 4n), warp
// tile 64x32 via m16n8k16. Smem tiles per stage: Ah, Al, Wh, Wl (8 KB each),
// 64 B row stride, 16B-chunk XOR swizzle c ^= (row>>1)&3.
// ---------------------------------------------------------------------------
__device__ __forceinline__ void load_stage(
    uint32_t sbase,
    const __nv_bfloat16* __restrict__ Ah, const __nv_bfloat16* __restrict__ Al,
    const __nv_bfloat16* __restrict__ Wh, const __nv_bfloat16* __restrict__ Wl,
    int m0, int n0, int k0, int tid)
{
#pragma unroll
    for (int j = 0; j < 2; j++) {
        int u   = tid + j * 256;
        int row = u >> 2;
        int c   = u & 3;
        uint32_t sw = (uint32_t)row * 64 + (uint32_t)((c ^ ((row >> 1) & 3)) * 16);
        size_t ka = (size_t)(m0 + row) * KPAD + k0 + c * 8;
        size_t kw = (size_t)(n0 + row) * KPAD + k0 + c * 8;
        CP16(sbase +     0 + sw, Ah + ka);
        CP16(sbase +  8192 + sw, Al + ka);
        CP16(sbase + 16384 + sw, Wh + kw);
        CP16(sbase + 24576 + sw, Wl + kw);
    }
}

__global__ __launch_bounds__(256, 2) void hmma_gemm_kernel(
    const __nv_bfloat16* __restrict__ Ah, const __nv_bfloat16* __restrict__ Al,
    const __nv_bfloat16* __restrict__ Wh, const __nv_bfloat16* __restrict__ Wl,
    const float* __restrict__ bias, float* __restrict__ C)
{
    extern __shared__ char smem[];
    const uint32_t smem_base = smem_u32(smem);

    const int tid  = threadIdx.x;
    const int wid  = tid >> 5;
    const int lane = tid & 31;
    const int wm   = wid & 1;    // m-offset wm*64
    const int wn   = wid >> 1;   // n-offset wn*32
    const int m0   = blockIdx.y * 128;
    const int n0   = blockIdx.x * 128;

    float acc[4][4][4];
#pragma unroll
    for (int i = 0; i < 4; i++)
#pragma unroll
        for (int j = 0; j < 4; j++)
#pragma unroll
            for (int k = 0; k < 4; k++) acc[i][j][k] = 0.0f;

    // prologue: stages 0,1
    load_stage(smem_base + 0 * STAGE_BYTES, Ah, Al, Wh, Wl, m0, n0, 0, tid);
    asm volatile("cp.async.commit_group;" ::: "memory");
    load_stage(smem_base + 1 * STAGE_BYTES, Ah, Al, Wh, Wl, m0, n0, BKT, tid);
    asm volatile("cp.async.commit_group;" ::: "memory");

    // ldmatrix lane-address components (stage-relative)
    const int arow_base = wm * 64 + (lane & 15);          // + mi*16
    const int abase_chk = lane >> 4;                      // + kk*2
    const int brow_base = wn * 32 + (lane & 7) + ((lane >> 1) & 8);  // + j*16
    const int bbase_chk = (lane >> 3) & 1;                // + kk*2

    int stage = 0;
    for (int it = 0; it < KT; it++) {
        asm volatile("cp.async.wait_group 1;" ::: "memory");
        __syncthreads();

        const uint32_t sbase = smem_base + (uint32_t)stage * STAGE_BYTES;

#pragma unroll
        for (int kk = 0; kk < 2; kk++) {
            uint32_t a_addr[4], b_addr[2];
#pragma unroll
            for (int mi = 0; mi < 4; mi++) {
                int r = arow_base + mi * 16;
                int c = (abase_chk + kk * 2) ^ ((r >> 1) & 3);
                a_addr[mi] = sbase + (uint32_t)(r * 64 + c * 16);
            }
#pragma unroll
            for (int j = 0; j < 2; j++) {
                int r = brow_base + j * 16;
                int c = (bbase_chk + kk * 2) ^ ((r >> 1) & 3);
                b_addr[j] = sbase + 16384u + (uint32_t)(r * 64 + c * 16);
            }

            uint32_t af[4][4], bh[4][2], bl[4][2];
#pragma unroll
            for (int mi = 0; mi < 4; mi++)       // Ah tile at +0
                ldsm_x4(a_addr[mi], af[mi][0], af[mi][1], af[mi][2], af[mi][3]);
#pragma unroll
            for (int j = 0; j < 2; j++) {        // Wh at +16384, Wl at +24576
                ldsm_x4(b_addr[j],         bh[2*j][0], bh[2*j][1], bh[2*j+1][0], bh[2*j+1][1]);
                ldsm_x4(b_addr[j] + 8192u, bl[2*j][0], bl[2*j][1], bl[2*j+1][0], bl[2*j+1][1]);
            }
#pragma unroll
            for (int mi = 0; mi < 4; mi++)
#pragma unroll
                for (int ni = 0; ni < 4; ni++) {
                    mma_bf16(acc[mi][ni], af[mi], bh[ni]);   // Ah*Wh
                    mma_bf16(acc[mi][ni], af[mi], bl[ni]);   // Ah*Wl
                }
#pragma unroll
            for (int mi = 0; mi < 4; mi++)       // Al tile at +8192 (reuse af regs)
                ldsm_x4(a_addr[mi] + 8192u, af[mi][0], af[mi][1], af[mi][2], af[mi][3]);
#pragma unroll
            for (int mi = 0; mi < 4; mi++)
#pragma unroll
                for (int ni = 0; ni < 4; ni++)
                    mma_bf16(acc[mi][ni], af[mi], bh[ni]);   // Al*Wh
        }

        // issue loads for stage it+2 into the buffer freed at the barrier above
        if (it + 2 < KT) {
            int ns = stage + 2; if (ns >= NSTAGES) ns -= NSTAGES;
            load_stage(smem_base + (uint32_t)ns * STAGE_BYTES,
                       Ah, Al, Wh, Wl, m0, n0, (it + 2) * BKT, tid);
        }
        asm volatile("cp.async.commit_group;" ::: "memory");

        stage++; if (stage == NSTAGES) stage = 0;
    }

    // epilogue: d0,d1 = (row g, col c,c+1); d2,d3 = (row g+8, col c,c+1)
    const int g = lane >> 2;
    const int q = lane & 3;
#pragma unroll
    for (int mi = 0; mi < 4; mi++) {
        const int row = m0 + wm * 64 + mi * 16 + g;
#pragma unroll
        for (int ni = 0; ni < 4; ni++) {
            const int col = n0 + wn * 32 + ni * 8 + q * 2;
            const float bv0 = bias[col], bv1 = bias[col + 1];
            float2 v0 = make_float2(acc[mi][ni][0] + bv0, acc[mi][ni][1] + bv1);
            float2 v1 = make_float2(acc[mi][ni][2] + bv0, acc[mi][ni][3] + bv1);
            *reinterpret_cast<float2*>(C + (size_t)row * HID + col)       = v0;
            *reinterpret_cast<float2*>(C + (size_t)(row + 8) * HID + col) = v1;
        }
    }
}

// ---------------------------------------------------------------------------
// Scan kernel (unchanged, known-good): one block per batch sample.
// ---------------------------------------------------------------------------
__global__ __launch_bounds__(1024, 1) void scan_kernel(
    const float* __restrict__ d1,     // [B*T, H], bias already included
    const float* __restrict__ tau1,   // [H]
    const float* __restrict__ W2,     // [O, H]
    const float* __restrict__ b2,     // [O]
    const float* __restrict__ tau2,   // [O]
    float* __restrict__ out)          // [B, O]
{
    const int b    = blockIdx.x;
    const int h    = threadIdx.x;
    const int warp = h >> 5;
    const int lane = h & 31;

    __shared__ float spk_sh[HID];
    __shared__ float d2_sh[OUTD];

    const float a1  = 1.0f / (1.0f + expf(-tau1[h]));
    const float om1 = 1.0f - a1;

    float w2r[32];
    if (warp < OUTD) {
#pragma unroll
        for (int i = 0; i < 32; i++)
            w2r[i] = W2[warp * HID + i * 32 + lane];
    }

    float mem2 = 0.0f, accum = 0.0f, a2 = 0.0f, om2 = 0.0f, bias2 = 0.0f;
    if (warp == 0 && lane < OUTD) {
        a2    = 1.0f / (1.0f + expf(-tau2[lane]));
        om2   = 1.0f - a2;
        bias2 = b2[lane];
    }

    float mem1 = 0.0f, spk = 0.0f;
    const float* d1b = d1 + (size_t)b * TSTEPS * HID + h;

    float dnext = d1b[0];
    for (int t = 0; t < TSTEPS; t++) {
        const float d = dnext;
        if (t < TSTEPS - 1) dnext = d1b[(size_t)(t + 1) * HID];

        mem1 = mem1 * a1 + om1 * d - spk;
        spk  = (mem1 > 1.0f) ? 1.0f : 0.0f;
        spk_sh[h] = spk;
        __syncthreads();

        if (warp < OUTD) {
            float s = 0.0f;
#pragma unroll
            for (int i = 0; i < 32; i++)
                s = fmaf(spk_sh[i * 32 + lane], w2r[i], s);
#pragma unroll
            for (int o = 16; o > 0; o >>= 1)
                s += __shfl_xor_sync(0xffffffffu, s, o);
            if (lane == 0) d2_sh[warp] = s;
        }
        __syncthreads();

        if (warp == 0) {
            float val = -3.402823466e38f;
            if (lane < OUTD) {
                mem2 = mem2 * a2 + om2 * (d2_sh[lane] + bias2);
                val  = mem2;
            }
            float m = val;
#pragma unroll
            for (int o = 16; o > 0; o >>= 1)
                m = fmaxf(m, __shfl_xor_sync(0xffffffffu, m, o));
            float e = (lane < OUTD) ? expf(val - m) : 0.0f;
            float ssum = e;
#pragma unroll
            for (int o = 16; o > 0; o >>= 1)
                ssum += __shfl_xor_sync(0xffffffffu, ssum, o);
            if (t > 10 && lane < OUTD)
                accum += e / ssum;
        }
        __syncthreads();
    }

    if (warp == 0 && lane < OUTD)
        out[b * OUTD + lane] = accum;
}

// ---------------------------------------------------------------------------
// kernel_launch
// ---------------------------------------------------------------------------
extern "C" void kernel_launch(void* const* d_in, const int* in_sizes, int n_in,
                              void* d_out, int out_size)
{
    const float* input = (const float*)d_in[0];
    const float* W1    = (const float*)d_in[1];
    const float* b1    = (const float*)d_in[2];
    const float* tau1  = (const float*)d_in[3];
    const float* W2    = (const float*)d_in[4];
    const float* b2    = (const float*)d_in[5];
    const float* tau2  = (const float*)d_in[6];
    float* out = (float*)d_out;

    float *d1;
    __nv_bfloat16 *Ah, *Al, *Wh, *Wl;
    cudaGetSymbolAddress((void**)&d1, g_d1);
    cudaGetSymbolAddress((void**)&Ah, g_Ah);
    cudaGetSymbolAddress((void**)&Al, g_Al);
    cudaGetSymbolAddress((void**)&Wh, g_Wh);
    cudaGetSymbolAddress((void**)&Wl, g_Wl);

    static int smem_set = 0;
    if (!smem_set) {
        cudaFuncSetAttribute(hmma_gemm_kernel,
                             cudaFuncAttributeMaxDynamicSharedMemorySize,
                             NSTAGES * STAGE_BYTES);
        smem_set = 1;
    }

    // Phase 0: split fp32 -> bf16 hi/lo (with K padding)
    split_bf16_kernel<<<4096, 256>>>(input, Ah, Al, MTOT);
    split_bf16_kernel<<<256, 256>>>(W1, Wh, Wl, HID);

    // Phase 1: d1 = A @ W1^T + b1 via warp-level bf16 HMMA (3-term split)
    dim3 grid(HID / 128, MTOT / 128);   // (8, 500)
    hmma_gemm_kernel<<<grid, 256, NSTAGES * STAGE_BYTES>>>(Ah, Al, Wh, Wl, b1, d1);

    // Phase 2: sequential scan
    scan_kernel<<<BATCH, HID>>>(d1, tau1, W2, b2, tau2, out);

    (void)in_sizes; (void)n_in; (void)out_size;
}